// round 1
// baseline (speedup 1.0000x reference)
#include <cuda_runtime.h>
#include <math.h>

#define BB 4
#define SS 2048
#define DD 2048

// Scratch: Q,K,V [B,S,D] and P [B,S,S] fp32. Static device globals (no cudaMalloc).
__device__ float g_Q[(size_t)BB * SS * DD];
__device__ float g_K[(size_t)BB * SS * DD];
__device__ float g_V[(size_t)BB * SS * DD];
__device__ float g_P[(size_t)BB * SS * SS];

// ---------------------------------------------------------------------------
// Tiled SGEMM: C[z] = alpha * A[z] @ op(B[z])
//   A: M x K row-major (lda = K)
//   TRANSB=false: B is K x N row-major (ldb = N)   -> C = A @ B
//   TRANSB=true : B is N x K row-major (ldb = K)   -> C = A @ B^T
// BM=BN=128, BK=16, 256 threads, 8x8 per thread. All dims multiples of tiles.
// ---------------------------------------------------------------------------
template <bool TRANSB>
__global__ __launch_bounds__(256) void sgemm_kernel(
    const float* __restrict__ A, const float* __restrict__ Bm,
    float* __restrict__ C, int M, int N, int K,
    size_t sA, size_t sB, size_t sC, float alpha)
{
    const int BM = 128, BN = 128, BK = 16, TM = 8, TN = 8;
    __shared__ float As[BK][BM + 4];
    __shared__ float Bs[BK][BN + 4];

    A  += (size_t)blockIdx.z * sA;
    Bm += (size_t)blockIdx.z * sB;
    C  += (size_t)blockIdx.z * sC;

    const int tid = threadIdx.x;
    const int tx = tid % 16;      // 0..15 -> col group
    const int ty = tid / 16;      // 0..15 -> row group
    const int rowBlock = blockIdx.y * BM;
    const int colBlock = blockIdx.x * BN;

    // A-tile loader mapping: each thread loads 2 float4 (rows tid/4 +{0,64})
    const int aRow = tid >> 2;          // 0..63
    const int aCol = (tid & 3) * 4;     // 0,4,8,12
    // B NN loader: rows tid/32 (+{0,8}), 4 floats at (tid%32)*4
    const int bRowNN = tid >> 5;        // 0..7
    const int bColNN = (tid & 31) * 4;  // 0..124

    float acc[TM][TN];
#pragma unroll
    for (int i = 0; i < TM; i++)
#pragma unroll
        for (int j = 0; j < TN; j++) acc[i][j] = 0.0f;

    float af[TM], bf[TN];

    for (int kt = 0; kt < K; kt += BK) {
        // ---- load A tile (transposed into As[k][m]) ----
#pragma unroll
        for (int off = 0; off < BM; off += 64) {
            float4 t = *reinterpret_cast<const float4*>(
                &A[(size_t)(rowBlock + aRow + off) * K + kt + aCol]);
            As[aCol + 0][aRow + off] = t.x;
            As[aCol + 1][aRow + off] = t.y;
            As[aCol + 2][aRow + off] = t.z;
            As[aCol + 3][aRow + off] = t.w;
        }
        // ---- load B tile into Bs[k][n] ----
        if (TRANSB) {
            // B is N x K row-major; need Bs[k][n] = B[n, k]
#pragma unroll
            for (int off = 0; off < BN; off += 64) {
                float4 t = *reinterpret_cast<const float4*>(
                    &Bm[(size_t)(colBlock + aRow + off) * K + kt + aCol]);
                Bs[aCol + 0][aRow + off] = t.x;
                Bs[aCol + 1][aRow + off] = t.y;
                Bs[aCol + 2][aRow + off] = t.z;
                Bs[aCol + 3][aRow + off] = t.w;
            }
        } else {
            // B is K x N row-major; direct vector copy
#pragma unroll
            for (int off = 0; off < BK; off += 8) {
                float4 t = *reinterpret_cast<const float4*>(
                    &Bm[(size_t)(kt + bRowNN + off) * N + colBlock + bColNN]);
                *reinterpret_cast<float4*>(&Bs[bRowNN + off][bColNN]) = t;
            }
        }
        __syncthreads();

#pragma unroll
        for (int k = 0; k < BK; k++) {
#pragma unroll
            for (int i = 0; i < TM; i++) af[i] = As[k][ty * TM + i];
#pragma unroll
            for (int j = 0; j < TN; j++) bf[j] = Bs[k][tx * TN + j];
#pragma unroll
            for (int i = 0; i < TM; i++)
#pragma unroll
                for (int j = 0; j < TN; j++) acc[i][j] += af[i] * bf[j];
        }
        __syncthreads();
    }

    // ---- write C ----
#pragma unroll
    for (int i = 0; i < TM; i++) {
        const size_t rowOff = (size_t)(rowBlock + ty * TM + i) * N + colBlock + tx * TN;
#pragma unroll
        for (int j4 = 0; j4 < TN; j4 += 4) {
            float4 o;
            o.x = acc[i][j4 + 0] * alpha;
            o.y = acc[i][j4 + 1] * alpha;
            o.z = acc[i][j4 + 2] * alpha;
            o.w = acc[i][j4 + 3] * alpha;
            *reinterpret_cast<float4*>(&C[rowOff + j4]) = o;
        }
    }
}

// ---------------------------------------------------------------------------
// Causal softmax over rows of P[b, row, :SS]. Valid length = row+1, rest -> 0.
// One block (256 threads) per row.
// ---------------------------------------------------------------------------
__global__ __launch_bounds__(256) void softmax_causal_kernel(float* __restrict__ P)
{
    const int row = blockIdx.x & (SS - 1);
    const int b   = blockIdx.x >> 11;   // SS = 2048 = 2^11
    float* p = P + ((size_t)b * SS + row) * SS;
    const int L = row + 1;
    const int tid = threadIdx.x;

    __shared__ float red[256];

    // max
    float m = -INFINITY;
    for (int i = tid; i < L; i += 256) m = fmaxf(m, p[i]);
    red[tid] = m; __syncthreads();
    for (int s = 128; s > 0; s >>= 1) {
        if (tid < s) red[tid] = fmaxf(red[tid], red[tid + s]);
        __syncthreads();
    }
    m = red[0]; __syncthreads();

    // exp + sum
    float sum = 0.0f;
    for (int i = tid; i < L; i += 256) {
        float e = __expf(p[i] - m);
        p[i] = e;
        sum += e;
    }
    red[tid] = sum; __syncthreads();
    for (int s = 128; s > 0; s >>= 1) {
        if (tid < s) red[tid] += red[tid + s];
        __syncthreads();
    }
    const float inv = 1.0f / red[0];
    __syncthreads();

    for (int i = tid; i < L; i += 256) p[i] *= inv;
    for (int i = L + tid; i < SS; i += 256) p[i] = 0.0f;
}

// ---------------------------------------------------------------------------
extern "C" void kernel_launch(void* const* d_in, const int* in_sizes, int n_in,
                              void* d_out, int out_size)
{
    const float* x  = (const float*)d_in[0];  // [B,S,D]
    const float* Wq = (const float*)d_in[1];  // [D,D]
    const float* Wk = (const float*)d_in[2];
    const float* Wv = (const float*)d_in[3];
    float* out = (float*)d_out;               // [B,S,D]

    float *Q, *K, *V, *P;
    cudaGetSymbolAddress((void**)&Q, g_Q);
    cudaGetSymbolAddress((void**)&K, g_K);
    cudaGetSymbolAddress((void**)&V, g_V);
    cudaGetSymbolAddress((void**)&P, g_P);

    const int M_qkv = BB * SS;      // 8192
    const dim3 blk(256);

    // QKV projections: [8192,2048] @ [2048,2048]
    dim3 gQKV(DD / 128, M_qkv / 128, 1);
    sgemm_kernel<false><<<gQKV, blk>>>(x, Wq, Q, M_qkv, DD, DD, 0, 0, 0, 1.0f);
    sgemm_kernel<false><<<gQKV, blk>>>(x, Wk, K, M_qkv, DD, DD, 0, 0, 0, 1.0f);
    sgemm_kernel<false><<<gQKV, blk>>>(x, Wv, V, M_qkv, DD, DD, 0, 0, 0, 1.0f);

    // scores: P[b] = (1/sqrt(D)) * Q[b] @ K[b]^T   [2048x2048]
    dim3 gAtt(SS / 128, SS / 128, BB);
    const float scale = 1.0f / sqrtf((float)DD);
    sgemm_kernel<true><<<gAtt, blk>>>(Q, K, P, SS, SS, DD,
                                      (size_t)SS * DD, (size_t)SS * DD,
                                      (size_t)SS * SS, scale);

    // causal softmax in place
    softmax_causal_kernel<<<BB * SS, blk>>>(P);

    // out[b] = P[b] @ V[b]
    sgemm_kernel<false><<<gAtt, blk>>>(P, V, out, SS, DD, SS,
                                       (size_t)SS * SS, (size_t)SS * DD,
                                       (size_t)SS * DD, 1.0f);
}

// round 3
// speedup vs baseline: 3.0535x; 3.0535x over previous
#include <cuda_runtime.h>
#include <cuda_bf16.h>
#include <cstdint>
#include <math.h>

#define BB 4
#define SS 2048
#define DD 2048
typedef __nv_bfloat16 bf16;

// ---------------- scratch (static device globals; no allocs) ----------------
__device__ bf16 g_xhi[(size_t)BB*SS*DD], g_xlo[(size_t)BB*SS*DD];
__device__ bf16 g_Wthi[3][(size_t)DD*DD], g_Wtlo[3][(size_t)DD*DD];
__device__ bf16 g_QKVhi[3][(size_t)BB*SS*DD], g_QKVlo[3][(size_t)BB*SS*DD];
__device__ bf16 g_Vthi[(size_t)BB*SS*DD], g_Vtlo[(size_t)BB*SS*DD];
__device__ float g_P[(size_t)BB*SS*SS];
__device__ bf16 g_Phi[(size_t)BB*SS*SS], g_Plo[(size_t)BB*SS*SS];

// ---------------- helpers ----------------
__device__ __forceinline__ uint32_t smem_u32(const void* p) {
    uint32_t a;
    asm("{ .reg .u64 t; cvta.to.shared.u64 t, %1; cvt.u32.u64 %0, t; }" : "=r"(a) : "l"(p));
    return a;
}
__device__ __forceinline__ void cp16(uint32_t dst, const void* src) {
    asm volatile("cp.async.cg.shared.global [%0], [%1], 16;" :: "r"(dst), "l"(src));
}
__device__ __forceinline__ void ldm4(uint32_t r[4], uint32_t addr) {
    asm volatile("ldmatrix.sync.aligned.m8n8.x4.shared.b16 {%0,%1,%2,%3}, [%4];"
                 : "=r"(r[0]), "=r"(r[1]), "=r"(r[2]), "=r"(r[3]) : "r"(addr));
}
__device__ __forceinline__ void mma16816(float c[4], const uint32_t a[4], const uint32_t b[2]) {
    asm volatile(
        "mma.sync.aligned.m16n8k16.row.col.f32.bf16.bf16.f32 "
        "{%0,%1,%2,%3}, {%4,%5,%6,%7}, {%8,%9}, {%0,%1,%2,%3};"
        : "+f"(c[0]), "+f"(c[1]), "+f"(c[2]), "+f"(c[3])
        : "r"(a[0]), "r"(a[1]), "r"(a[2]), "r"(a[3]), "r"(b[0]), "r"(b[1]));
}
__device__ __forceinline__ uint32_t pack2(bf16 a, bf16 b) {
    return (uint32_t)__bfloat16_as_ushort(a) | ((uint32_t)__bfloat16_as_ushort(b) << 16);
}

// ---------------- GEMM: C[z] = alpha * A[z] @ B[z]^T via bf16 hi/lo x3 HMMA ----
// A: [M,K] rows, B: [N,K] rows (both K-major). EPI 0: fp32 out. EPI 1: split bf16 out.
// MODE 0: dense. MODE 1: skip tiles fully above causal diag. MODE 2: K truncated at m0+128.
#define BK_ 32
#define RSTRIDE 80                  // 64B data + 16B pad per row
#define ARR_BYTES (128 * RSTRIDE)   // 10240
#define OFF_AHI 0
#define OFF_ALO ARR_BYTES
#define OFF_BHI (2 * ARR_BYTES)
#define OFF_BLO (3 * ARR_BYTES)
#define STAGE_BYTES (4 * ARR_BYTES) // 40960
#define NSTAGE 4
#define SMEM_GEMM (NSTAGE * STAGE_BYTES)  // 163840

template<int EPI, int MODE>
__global__ void __launch_bounds__(256, 1)
gemm_hmma(const bf16* __restrict__ Ahi, const bf16* __restrict__ Alo,
          const bf16* __restrict__ Bhi, const bf16* __restrict__ Blo,
          float* __restrict__ Cf, bf16* __restrict__ Chi, bf16* __restrict__ Clo,
          int M, int N, int K, size_t sA, size_t sB, size_t sC, float alpha)
{
    const int m0 = blockIdx.y * 128;
    const int n0 = blockIdx.x * 128;
    const int z  = blockIdx.z;
    if (MODE == 1 && n0 > m0) return;     // fully-masked score tile
    int KT = K / BK_;
    if (MODE == 2) { int kmax = m0 + 128; if (kmax < K) KT = kmax / BK_; }

    extern __shared__ char smem[];
    const uint32_t sbase = smem_u32(smem);
    const int tid  = threadIdx.x;
    const int lane = tid & 31;
    const int wid  = tid >> 5;
    const int wm   = (wid >> 2) * 64;     // warp row offset (0/64)
    const int wn   = (wid & 3) * 32;      // warp col offset (0/32/64/96)

    const bf16* pAhi = Ahi + (size_t)z * sA;
    const bf16* pAlo = Alo + (size_t)z * sA;
    const bf16* pBhi = Bhi + (size_t)z * sB;
    const bf16* pBlo = Blo + (size_t)z * sB;

    // loader mapping: rows r, r+64; 16B segment sg
    const int lr = tid >> 2;
    const int sg = tid & 3;

    auto load_stage = [&](int s, int kt) {
        if (kt < KT) {
            const uint32_t st = sbase + (uint32_t)s * STAGE_BYTES;
            const size_t ko = (size_t)kt * BK_ + sg * 8;
            const uint32_t so = (uint32_t)(lr * RSTRIDE + sg * 16);
            cp16(st + OFF_AHI + so,       pAhi + (size_t)(m0 + lr) * K + ko);
            cp16(st + OFF_AHI + so + 64*RSTRIDE, pAhi + (size_t)(m0 + lr + 64) * K + ko);
            cp16(st + OFF_ALO + so,       pAlo + (size_t)(m0 + lr) * K + ko);
            cp16(st + OFF_ALO + so + 64*RSTRIDE, pAlo + (size_t)(m0 + lr + 64) * K + ko);
            cp16(st + OFF_BHI + so,       pBhi + (size_t)(n0 + lr) * K + ko);
            cp16(st + OFF_BHI + so + 64*RSTRIDE, pBhi + (size_t)(n0 + lr + 64) * K + ko);
            cp16(st + OFF_BLO + so,       pBlo + (size_t)(n0 + lr) * K + ko);
            cp16(st + OFF_BLO + so + 64*RSTRIDE, pBlo + (size_t)(n0 + lr + 64) * K + ko);
        }
        asm volatile("cp.async.commit_group;" ::: "memory");
    };

    // per-lane ldmatrix address components
    const int arow = lane & 15;            // row within 16-row tile
    const int akh  = lane >> 4;            // k half (16B)
    const int nrow = (lane & 7) + ((lane >> 4) << 3);
    const int bkh  = (lane >> 3) & 1;
    const uint32_t aoff = (uint32_t)((wm + arow) * RSTRIDE + akh * 16);
    const uint32_t boff = (uint32_t)((wn + nrow) * RSTRIDE + bkh * 16);

    float acc[4][4][4];
#pragma unroll
    for (int i = 0; i < 4; i++)
#pragma unroll
        for (int j = 0; j < 4; j++)
#pragma unroll
            for (int q = 0; q < 4; q++) acc[i][j][q] = 0.0f;

    load_stage(0, 0);
    load_stage(1, 1);
    load_stage(2, 2);

    for (int it = 0; it < KT; it++) {
        const int s = it & (NSTAGE - 1);
        asm volatile("cp.async.wait_group 2;" ::: "memory");
        __syncthreads();
        const uint32_t stg = sbase + (uint32_t)s * STAGE_BYTES;
#pragma unroll
        for (int ks = 0; ks < 2; ks++) {
            uint32_t ah[4][4], al[4][4], bh[4][2], bl[4][2];
#pragma unroll
            for (int mt = 0; mt < 4; mt++) {
                ldm4(ah[mt], stg + OFF_AHI + aoff + mt * (16 * RSTRIDE) + ks * 32);
                ldm4(al[mt], stg + OFF_ALO + aoff + mt * (16 * RSTRIDE) + ks * 32);
            }
#pragma unroll
            for (int ntp = 0; ntp < 2; ntp++) {
                uint32_t t[4];
                ldm4(t, stg + OFF_BHI + boff + ntp * (16 * RSTRIDE) + ks * 32);
                bh[2*ntp][0] = t[0]; bh[2*ntp][1] = t[1];
                bh[2*ntp+1][0] = t[2]; bh[2*ntp+1][1] = t[3];
                ldm4(t, stg + OFF_BLO + boff + ntp * (16 * RSTRIDE) + ks * 32);
                bl[2*ntp][0] = t[0]; bl[2*ntp][1] = t[1];
                bl[2*ntp+1][0] = t[2]; bl[2*ntp+1][1] = t[3];
            }
#pragma unroll
            for (int mt = 0; mt < 4; mt++)
#pragma unroll
                for (int nt = 0; nt < 4; nt++) {
                    mma16816(acc[mt][nt], ah[mt], bh[nt]);
                    mma16816(acc[mt][nt], ah[mt], bl[nt]);
                    mma16816(acc[mt][nt], al[mt], bh[nt]);
                }
        }
        load_stage((it + 3) & (NSTAGE - 1), it + 3);
    }

    // ---- epilogue (from registers) ----
    const int r0 = wm + (lane >> 2);
    const int c0 = wn + (lane & 3) * 2;
#pragma unroll
    for (int mt = 0; mt < 4; mt++) {
#pragma unroll
        for (int nt = 0; nt < 4; nt++) {
            const int row = m0 + r0 + mt * 16;
            const int col = n0 + c0 + nt * 8;
            float v0 = acc[mt][nt][0] * alpha, v1 = acc[mt][nt][1] * alpha;
            float v2 = acc[mt][nt][2] * alpha, v3 = acc[mt][nt][3] * alpha;
            if (EPI == 0) {
                float* d0 = Cf + (size_t)z * sC + (size_t)row * N + col;
                float* d1 = Cf + (size_t)z * sC + (size_t)(row + 8) * N + col;
                d0[0] = v0; d0[1] = v1;
                d1[0] = v2; d1[1] = v3;
            } else {
                bf16 h0 = __float2bfloat16(v0), h1 = __float2bfloat16(v1);
                bf16 h2 = __float2bfloat16(v2), h3 = __float2bfloat16(v3);
                bf16 l0 = __float2bfloat16(v0 - __bfloat162float(h0));
                bf16 l1 = __float2bfloat16(v1 - __bfloat162float(h1));
                bf16 l2 = __float2bfloat16(v2 - __bfloat162float(h2));
                bf16 l3 = __float2bfloat16(v3 - __bfloat162float(h3));
                size_t o0 = (size_t)z * sC + (size_t)row * N + col;
                size_t o1 = (size_t)z * sC + (size_t)(row + 8) * N + col;
                *reinterpret_cast<uint32_t*>(Chi + o0) = pack2(h0, h1);
                *reinterpret_cast<uint32_t*>(Chi + o1) = pack2(h2, h3);
                *reinterpret_cast<uint32_t*>(Clo + o0) = pack2(l0, l1);
                *reinterpret_cast<uint32_t*>(Clo + o1) = pack2(l2, l3);
            }
        }
    }
}

// ---------------- conversion / transpose / softmax ----------------
__global__ __launch_bounds__(256) void split_kernel(
    const float* __restrict__ in, bf16* __restrict__ hi, bf16* __restrict__ lo, size_t n)
{
    for (size_t i = (size_t)blockIdx.x * 256 + threadIdx.x; i < n; i += (size_t)gridDim.x * 256) {
        float v = in[i];
        bf16 h = __float2bfloat16(v);
        hi[i] = h;
        lo[i] = __float2bfloat16(v - __bfloat162float(h));
    }
}

__global__ void transpose_split_kernel(const float* __restrict__ in,
                                       bf16* __restrict__ hi, bf16* __restrict__ lo)
{
    __shared__ float t[32][33];
    const int c0 = blockIdx.x * 32, rr0 = blockIdx.y * 32;
    const int tx = threadIdx.x, ty = threadIdx.y;
#pragma unroll
    for (int j = 0; j < 32; j += 8)
        t[ty + j][tx] = in[(size_t)(rr0 + ty + j) * DD + c0 + tx];
    __syncthreads();
#pragma unroll
    for (int j = 0; j < 32; j += 8) {
        float v = t[tx][ty + j];
        bf16 h = __float2bfloat16(v);
        size_t o = (size_t)(c0 + ty + j) * DD + rr0 + tx;
        hi[o] = h;
        lo[o] = __float2bfloat16(v - __bfloat162float(h));
    }
}

__global__ void transpose_bf16_kernel(const bf16* __restrict__ in, bf16* __restrict__ out)
{
    __shared__ bf16 t[32][33];
    const int b = blockIdx.z;
    const int d0 = blockIdx.x * 32, s0 = blockIdx.y * 32;
    const int tx = threadIdx.x, ty = threadIdx.y;
    const bf16* src = in + (size_t)b * SS * DD;
    bf16* dst = out + (size_t)b * DD * SS;
#pragma unroll
    for (int j = 0; j < 32; j += 8)
        t[ty + j][tx] = src[(size_t)(s0 + ty + j) * DD + d0 + tx];
    __syncthreads();
#pragma unroll
    for (int j = 0; j < 32; j += 8)
        dst[(size_t)(d0 + ty + j) * SS + s0 + tx] = t[tx][ty + j];
}

__global__ __launch_bounds__(256) void softmax_split_kernel(
    const float* __restrict__ P, bf16* __restrict__ Phi, bf16* __restrict__ Plo)
{
    const int row = blockIdx.x & (SS - 1);
    const int b   = blockIdx.x >> 11;
    const size_t base = ((size_t)b * SS + row) * SS;
    const int L = row + 1;
    const int tid = threadIdx.x;

    float v[8];
    float m = -INFINITY;
#pragma unroll
    for (int j = 0; j < 8; j++) {
        int i = tid + j * 256;
        v[j] = (i < L) ? P[base + i] : -INFINITY;
        m = fmaxf(m, v[j]);
    }
    __shared__ float red[256];
    red[tid] = m; __syncthreads();
    for (int s2 = 128; s2 > 0; s2 >>= 1) {
        if (tid < s2) red[tid] = fmaxf(red[tid], red[tid + s2]);
        __syncthreads();
    }
    m = red[0]; __syncthreads();

    float sum = 0.0f;
#pragma unroll
    for (int j = 0; j < 8; j++) {
        int i = tid + j * 256;
        if (i < L) { v[j] = __expf(v[j] - m); sum += v[j]; }
    }
    red[tid] = sum; __syncthreads();
    for (int s2 = 128; s2 > 0; s2 >>= 1) {
        if (tid < s2) red[tid] += red[tid + s2];
        __syncthreads();
    }
    const float inv = 1.0f / red[0];
    __syncthreads();

#pragma unroll
    for (int j = 0; j < 8; j++) {
        int i = tid + j * 256;
        if (i < L) {
            float val = v[j] * inv;
            bf16 h = __float2bfloat16(val);
            Phi[base + i] = h;
            Plo[base + i] = __float2bfloat16(val - __bfloat162float(h));
        }
    }
    const bf16 z16 = __float2bfloat16(0.0f);
    for (int i = L + tid; i < SS; i += 256) { Phi[base + i] = z16; Plo[base + i] = z16; }
}

// ---------------- launch ----------------
extern "C" void kernel_launch(void* const* d_in, const int* in_sizes, int n_in,
                              void* d_out, int out_size)
{
    const float* x  = (const float*)d_in[0];
    const float* Wq = (const float*)d_in[1];
    const float* Wk = (const float*)d_in[2];
    const float* Wv = (const float*)d_in[3];
    float* out = (float*)d_out;

    bf16 *xhi, *xlo, *Wthi, *Wtlo, *QKVhi, *QKVlo, *Vthi, *Vtlo, *Phi, *Plo;
    float* P;
    cudaGetSymbolAddress((void**)&xhi,   g_xhi);
    cudaGetSymbolAddress((void**)&xlo,   g_xlo);
    cudaGetSymbolAddress((void**)&Wthi,  g_Wthi);
    cudaGetSymbolAddress((void**)&Wtlo,  g_Wtlo);
    cudaGetSymbolAddress((void**)&QKVhi, g_QKVhi);
    cudaGetSymbolAddress((void**)&QKVlo, g_QKVlo);
    cudaGetSymbolAddress((void**)&Vthi,  g_Vthi);
    cudaGetSymbolAddress((void**)&Vtlo,  g_Vtlo);
    cudaGetSymbolAddress((void**)&P,     g_P);
    cudaGetSymbolAddress((void**)&Phi,   g_Phi);
    cudaGetSymbolAddress((void**)&Plo,   g_Plo);

    cudaFuncSetAttribute(gemm_hmma<1,0>, cudaFuncAttributeMaxDynamicSharedMemorySize, SMEM_GEMM);
    cudaFuncSetAttribute(gemm_hmma<0,1>, cudaFuncAttributeMaxDynamicSharedMemorySize, SMEM_GEMM);
    cudaFuncSetAttribute(gemm_hmma<0,2>, cudaFuncAttributeMaxDynamicSharedMemorySize, SMEM_GEMM);

    const size_t WSZ = (size_t)DD * DD;
    const size_t QSZ = (size_t)BB * SS * DD;
    const dim3 t32(32, 8);

    // convert inputs
    split_kernel<<<8192, 256>>>(x, xhi, xlo, QSZ);
    transpose_split_kernel<<<dim3(DD/32, DD/32), t32>>>(Wq, Wthi + 0*WSZ, Wtlo + 0*WSZ);
    transpose_split_kernel<<<dim3(DD/32, DD/32), t32>>>(Wk, Wthi + 1*WSZ, Wtlo + 1*WSZ);
    transpose_split_kernel<<<dim3(DD/32, DD/32), t32>>>(Wv, Wthi + 2*WSZ, Wtlo + 2*WSZ);

    // QKV projections in one launch: z in {0,1,2} selects W slice and output slice
    dim3 g1(DD/128, (BB*SS)/128, 3);
    gemm_hmma<1,0><<<g1, 256, SMEM_GEMM>>>(xhi, xlo, Wthi, Wtlo,
                                           nullptr, QKVhi, QKVlo,
                                           BB*SS, DD, DD, 0, WSZ, QSZ, 1.0f);

    // V^T for PV GEMM's B operand
    transpose_bf16_kernel<<<dim3(DD/32, SS/32, BB), t32>>>(QKVhi + 2*QSZ, Vthi);
    transpose_bf16_kernel<<<dim3(DD/32, SS/32, BB), t32>>>(QKVlo + 2*QSZ, Vtlo);

    // scores: P[b] = scale * Q[b] @ K[b]^T (skip fully-masked tiles)
    dim3 g2(SS/128, SS/128, BB);
    const float scale = 1.0f / sqrtf((float)DD);
    gemm_hmma<0,1><<<g2, 256, SMEM_GEMM>>>(QKVhi, QKVlo, QKVhi + QSZ, QKVlo + QSZ,
                                           P, nullptr, nullptr,
                                           SS, SS, DD, (size_t)SS*DD, (size_t)SS*DD,
                                           (size_t)SS*SS, scale);

    // causal softmax -> split bf16 P
    softmax_split_kernel<<<BB * SS, 256>>>(P, Phi, Plo);

    // out[b] = P[b] @ V[b] (K truncated at diagonal)
    dim3 g3(DD/128, SS/128, BB);
    gemm_hmma<0,2><<<g3, 256, SMEM_GEMM>>>(Phi, Plo, Vthi, Vtlo,
                                           out, nullptr, nullptr,
                                           SS, DD, SS, (size_t)SS*SS, (size_t)SS*DD,
                                           (size_t)SS*DD, 1.0f);
}